// round 6
// baseline (speedup 1.0000x reference)
#include <cuda_runtime.h>
#include <cstdint>

// Problem constants
#define B_    4096
#define T_    512
#define D_    64
#define H_    128
#define A_    8

#define CLSZ  4       // CTAs per cluster
#define BB    128     // batch rows per cluster
#define JH    32      // hidden units per CTA (4 CTAs cover H=128)
#define NTHR  512     // 16 warps; warp w owns CTA-local j pair [2w, 2w+2)
#define KTOT  192     // fused K: 64 (x_t) + 128 (h)

// Dynamic smem layout:
//   Ws : [192 k][4 g][32 j]  fp32 -> 24576 floats (98304 B)
//   act: [192 k][128 b]      fp32 -> rows 0..63 = x_t[d][b], 64..191 = h[j][b]
#define W_ELEMS    (KTOT * 4 * JH)
#define ACT_ELEMS  (KTOT * BB)
#define SMEM_BYTES ((W_ELEMS + ACT_ELEMS) * 4)   // 196608 B

// ----------------- helpers -----------------

__device__ __forceinline__ uint32_t s2u(const void* p) {
    uint32_t a;
    asm("{ .reg .u64 t; cvta.to.shared.u64 t, %1; cvt.u32.u64 %0, t; }"
        : "=r"(a) : "l"(p));
    return a;
}

__device__ __forceinline__ void cluster_sync_() {
    asm volatile("barrier.cluster.arrive.aligned;" ::: "memory");
    asm volatile("barrier.cluster.wait.aligned;" ::: "memory");
}

__device__ __forceinline__ unsigned long long pack2(float x, float y) {
    unsigned long long r;
    asm("mov.b64 %0, {%1, %2};" : "=l"(r) : "f"(x), "f"(y));
    return r;
}
__device__ __forceinline__ void unpack2(unsigned long long v, float& x, float& y) {
    asm("mov.b64 {%0, %1}, %2;" : "=f"(x), "=f"(y) : "l"(v));
}

// fast, overflow-safe sigmoid / tanh (~1e-6 accuracy, MUFU-based)
__device__ __forceinline__ float sigf(float x) {
    return __fdividef(1.0f, 1.0f + __expf(-x));
}
__device__ __forceinline__ float tanh_f(float x) {
    float e = __expf(-2.0f * fabsf(x));
    float r = __fdividef(1.0f - e, 1.0f + e);
    return copysignf(r, x);
}

// One broadcast weight-pair load feeding 4 batch columns (4 FFMA2).
// wk already includes this warp's j-pair byte offset (warp*2*4).
#define WFMA(g)                                                                     \
    {                                                                               \
        unsigned long long wv;                                                      \
        asm volatile("ld.shared.b64 %0, [%1+%2];"                                   \
                     : "=l"(wv) : "r"(wk), "n"((g) * JH * 4));                      \
        asm("fma.rn.f32x2 %0, %1, %2, %0;" : "+l"(acc[(g)*4+0]) : "l"(wv), "l"(av0)); \
        asm("fma.rn.f32x2 %0, %1, %2, %0;" : "+l"(acc[(g)*4+1]) : "l"(wv), "l"(av1)); \
        asm("fma.rn.f32x2 %0, %1, %2, %0;" : "+l"(acc[(g)*4+2]) : "l"(wv), "l"(av2)); \
        asm("fma.rn.f32x2 %0, %1, %2, %0;" : "+l"(acc[(g)*4+3]) : "l"(wv), "l"(av3)); \
    }

union F4 { float4 v; float f[4]; };

__global__ void __launch_bounds__(NTHR, 1) __cluster_dims__(CLSZ, 1, 1)
lstm_fused_kernel(const float* __restrict__ state,   // [B, T, D]
                  const float* __restrict__ W_ih,    // [4H, D]
                  const float* __restrict__ W_hh,    // [4H, H]
                  const float* __restrict__ b_ih,    // [4H]
                  const float* __restrict__ b_hh,    // [4H]
                  const float* __restrict__ W_fc,    // [A, H]
                  const float* __restrict__ b_fc,    // [A]
                  float* __restrict__ out)           // [B, A]
{
    extern __shared__ float smem[];
    float* Ws  = smem;               // [(k*4 + g)*32 + jl]
    float* act = smem + W_ELEMS;     // [k*128 + b]

    const int tid  = threadIdx.x;
    const int lane = tid & 31;
    const int warp = tid >> 5;       // 0..15
    const int jb   = warp * 2;       // CTA-local j pair base
    const int d0   = warp * 4;       // x-dims owned for load/store
    const int bloc = lane * 4;       // this thread's 4 batch columns [bloc, bloc+4)

    uint32_t rank;
    asm("mov.u32 %0, %%cluster_ctarank;" : "=r"(rank));
    const int b0  = (blockIdx.x >> 2) * BB;   // cluster's global batch base
    const int jg0 = (int)rank * JH;           // this CTA's global j offset

    // ---- Fill Ws (coalesced over k in global memory) ----
    for (int e = tid; e < 4 * JH * D_; e += NTHR) {       // x-part k in [0,64)
        int k  = e & 63;
        int rl = e >> 6;
        int g  = rl >> 5;
        int jl = rl & 31;
        Ws[(k * 4 + g) * JH + jl] = W_ih[(g * H_ + jg0 + jl) * D_ + k];
    }
    for (int e = tid; e < 4 * JH * H_; e += NTHR) {       // h-part k in [64,192)
        int k  = e & 127;
        int rl = e >> 7;
        int g  = rl >> 5;
        int jl = rl & 31;
        Ws[((64 + k) * 4 + g) * JH + jl] = W_hh[(g * H_ + jg0 + jl) * H_ + k];
    }

    // ---- init act: h rows (64..191) = 0 ----
    for (int e = tid; e < H_ * BB; e += NTHR)
        act[(D_ + (e >> 7)) * BB + (e & 127)] = 0.0f;

    // ---- x_0 into act rows 0..63 ----
    {
        F4 x[4];
#pragma unroll
        for (int q = 0; q < 4; q++)
            x[q].v = *(const float4*)(state + (size_t)(b0 + bloc + q) * T_ * D_ + d0);
#pragma unroll
        for (int i = 0; i < 4; i++)
            *(float4*)(act + (d0 + i) * BB + bloc) =
                make_float4(x[0].f[i], x[1].f[i], x[2].f[i], x[3].f[i]);
    }

    // ---- bias preload (per g, for this warp's j pair; column-independent) ----
    unsigned long long bias2[4];
#pragma unroll
    for (int g = 0; g < 4; g++) {
        int r = g * H_ + jg0 + jb;
        bias2[g] = pack2(b_ih[r] + b_hh[r], b_ih[r + 1] + b_hh[r + 1]);
    }

    float c[8];   // [q*2 + jj]
#pragma unroll
    for (int i = 0; i < 8; i++) c[i] = 0.0f;

    const uint32_t act_u = s2u(act);
    const uint32_t W_u   = s2u(Ws);
    const uint32_t ak0   = act_u + (uint32_t)bloc * 4;     // + lane*16
    const uint32_t wk0   = W_u + (uint32_t)jb * 4;
    // local h-store base: row (64 + jg0 + jb), cols bloc..bloc+3
    const uint32_t h0addr = act_u + (uint32_t)(D_ + jg0 + jb) * BB * 4 + (uint32_t)bloc * 4;

    __syncthreads();   // Ws/act init visible CTA-locally (first step reads local only)

    for (int t = 0; t < T_; t++) {
        // prefetch x_{t+1} into registers (consumed after cluster sync #1)
        F4 xp[4];
        if (t < T_ - 1) {
#pragma unroll
            for (int q = 0; q < 4; q++)
                xp[q].v = *(const float4*)(state + (size_t)(b0 + bloc + q) * T_ * D_
                                           + (t + 1) * D_ + d0);
        }

        // ---- gates = Ws^T * act + bias (2 j x 4 g x 4 cols per thread) ----
        unsigned long long acc[16];
#pragma unroll
        for (int g = 0; g < 4; g++) {
            acc[g * 4 + 0] = bias2[g];
            acc[g * 4 + 1] = bias2[g];
            acc[g * 4 + 2] = bias2[g];
            acc[g * 4 + 3] = bias2[g];
        }

        uint32_t ak = ak0, wk = wk0;
#pragma unroll 4
        for (int k = 0; k < KTOT; k++) {
            float a0, a1, a2, a3;
            asm volatile("ld.shared.v4.f32 {%0,%1,%2,%3}, [%4];"
                         : "=f"(a0), "=f"(a1), "=f"(a2), "=f"(a3) : "r"(ak));
            unsigned long long av0 = pack2(a0, a0);
            unsigned long long av1 = pack2(a1, a1);
            unsigned long long av2 = pack2(a2, a2);
            unsigned long long av3 = pack2(a3, a3);
            WFMA(0) WFMA(1) WFMA(2) WFMA(3)
            ak += BB * 4;        // 512 B per k row
            wk += 4 * JH * 4;    // 512 B per k row
        }

        // ---- activations: i,f,g,o -> c, h ----
        float hv[8];   // [q*2 + jj]
#pragma unroll
        for (int q = 0; q < 4; q++) {
            float i0, i1, f0, f1, g0, g1, o0, o1;
            unpack2(acc[0 * 4 + q], i0, i1);
            unpack2(acc[1 * 4 + q], f0, f1);
            unpack2(acc[2 * 4 + q], g0, g1);
            unpack2(acc[3 * 4 + q], o0, o1);
            {
                float cn = sigf(f0) * c[q * 2 + 0] + sigf(i0) * tanh_f(g0);
                c[q * 2 + 0]  = cn;
                hv[q * 2 + 0] = sigf(o0) * tanh_f(cn);
            }
            {
                float cn = sigf(f1) * c[q * 2 + 1] + sigf(i1) * tanh_f(g1);
                c[q * 2 + 1]  = cn;
                hv[q * 2 + 1] = sigf(o1) * tanh_f(cn);
            }
        }

        cluster_sync_();   // #1: all CTAs done READING act

        // ---- store my h (2 j x 4 cols): local v4 + 3 remote peers (scalar) ----
#pragma unroll
        for (int jj = 0; jj < 2; jj++) {
            uint32_t addr = h0addr + (uint32_t)jj * BB * 4;
            asm volatile("st.shared.v4.f32 [%0], {%1,%2,%3,%4};"
                         :: "r"(addr), "f"(hv[0 * 2 + jj]), "f"(hv[1 * 2 + jj]),
                            "f"(hv[2 * 2 + jj]), "f"(hv[3 * 2 + jj]) : "memory");
        }
#pragma unroll
        for (int pr = 0; pr < CLSZ; pr++) {
            if (pr == (int)rank) continue;
            uint32_t ra;
            asm volatile("mapa.shared::cluster.u32 %0, %1, %2;"
                         : "=r"(ra) : "r"(h0addr), "r"((uint32_t)pr));
#pragma unroll
            for (int jj = 0; jj < 2; jj++) {
#pragma unroll
                for (int q = 0; q < 4; q++) {
                    asm volatile("st.shared::cluster.f32 [%0], %1;"
                                 :: "r"(ra + (uint32_t)(jj * BB * 4 + q * 4)),
                                    "f"(hv[q * 2 + jj]) : "memory");
                }
            }
        }

        // ---- store x_{t+1} ----
        if (t < T_ - 1) {
#pragma unroll
            for (int i = 0; i < 4; i++)
                *(float4*)(act + (d0 + i) * BB + bloc) =
                    make_float4(xp[0].f[i], xp[1].f[i], xp[2].f[i], xp[3].f[i]);
        }

        cluster_sync_();   // #2: all writes (incl. remote h) visible before next read
    }

    // ---- FC epilogue: out = tanh(h @ W_fc^T + b_fc) ----
    // act rows 64..191 hold final h for all 128 units x all 128 cluster batches.
    // CTA rank handles batch cols [rank*32, rank*32+32); warps 0..7 -> a = warp.
    if (warp < A_) {
        int a   = warp;
        int col = (int)rank * 32 + lane;
        float s = b_fc[a];
        const float* wf = W_fc + a * H_;
#pragma unroll 8
        for (int j = 0; j < H_; j++)
            s += act[(D_ + j) * BB + col] * wf[j];
        out[(size_t)(b0 + col) * A_ + a] = tanhf(s);
    }
}

extern "C" void kernel_launch(void* const* d_in, const int* in_sizes, int n_in,
                              void* d_out, int out_size) {
    (void)in_sizes; (void)n_in; (void)out_size;
    cudaFuncSetAttribute(lstm_fused_kernel,
                         cudaFuncAttributeMaxDynamicSharedMemorySize, SMEM_BYTES);
    const float* state = (const float*)d_in[0];
    const float* W_ih  = (const float*)d_in[1];
    const float* W_hh  = (const float*)d_in[2];
    const float* b_ih  = (const float*)d_in[3];
    const float* b_hh  = (const float*)d_in[4];
    const float* W_fc  = (const float*)d_in[5];
    const float* b_fc  = (const float*)d_in[6];

    dim3 grid((B_ / BB) * CLSZ);   // 128 CTAs = 32 clusters of 4 -> single wave
    lstm_fused_kernel<<<grid, NTHR, SMEM_BYTES>>>(
        state, W_ih, W_hh, b_ih, b_hh, W_fc, b_fc, (float*)d_out);
}

// round 9
// speedup vs baseline: 3.4243x; 3.4243x over previous
#include <cuda_runtime.h>
#include <cuda_bf16.h>
#include <cstdint>

#define B_   4096
#define T_   512
#define D_   64
#define H_   128
#define A_   8

#define CLSZ 4
#define MB   128     // batch rows per cluster (M)
#define NTHR 512     // 16 warps: warp tile 32m x 32n

// smem: four [128 x 192] bf16 tiles, SW128 blocked atoms (16 atomrows x 3 atomcols)
#define TILE     49152
#define OFF_AHI  0
#define OFF_ALO  49152
#define OFF_WHI  98304
#define OFF_WLO  147456
#define SMEM_BYTES 196608

// ---------------- helpers ----------------
static __device__ __forceinline__ uint32_t s2u(const void* p) {
    uint32_t a;
    asm("{ .reg .u64 t; cvta.to.shared.u64 t, %1; cvt.u32.u64 %0, t; }" : "=r"(a) : "l"(p));
    return a;
}
static __device__ __forceinline__ void cluster_sync_() {
    asm volatile("barrier.cluster.arrive.aligned;" ::: "memory");
    asm volatile("barrier.cluster.wait.aligned;" ::: "memory");
}
static __device__ __forceinline__ uint32_t mapa_(uint32_t a, uint32_t r) {
    uint32_t d;
    asm("mapa.shared::cluster.u32 %0, %1, %2;" : "=r"(d) : "r"(a), "r"(r));
    return d;
}
static __device__ __forceinline__ void ldm4(uint32_t* r, uint32_t addr) {
    asm volatile("ldmatrix.sync.aligned.m8n8.x4.shared.b16 {%0,%1,%2,%3}, [%4];"
                 : "=r"(r[0]), "=r"(r[1]), "=r"(r[2]), "=r"(r[3]) : "r"(addr));
}
static __device__ __forceinline__ void mma_bf16(float* d, const uint32_t* a,
                                                const uint32_t* b) {
    asm volatile("mma.sync.aligned.m16n8k16.row.col.f32.bf16.bf16.f32 "
                 "{%0,%1,%2,%3}, {%4,%5,%6,%7}, {%8,%9}, {%0,%1,%2,%3};"
                 : "+f"(d[0]), "+f"(d[1]), "+f"(d[2]), "+f"(d[3])
                 : "r"(a[0]), "r"(a[1]), "r"(a[2]), "r"(a[3]), "r"(b[0]), "r"(b[1]));
}
static __device__ __forceinline__ void stc32(uint32_t a, uint32_t v) {
    asm volatile("st.shared::cluster.b32 [%0], %1;" :: "r"(a), "r"(v) : "memory");
}
static __device__ __forceinline__ void stv4(uint32_t a, const uint32_t* v) {
    asm volatile("st.shared.v4.b32 [%0], {%1,%2,%3,%4};"
                 :: "r"(a), "r"(v[0]), "r"(v[1]), "r"(v[2]), "r"(v[3]) : "memory");
}
// byte offset of (row, k) in a [128 x 192] bf16 blocked-SW128 tile (generic/init path)
static __device__ __forceinline__ uint32_t aoff(int row, int k) {
    uint32_t b = (uint32_t)(((row >> 3) + (k >> 6) * 16) * 1024
                            + (row & 7) * 128 + (k & 63) * 2);
    return b ^ ((b >> 3) & 0x70);
}
// fast overflow-safe sigmoid / tanh (MUFU ex2/rcp, ~1e-6)
static __device__ __forceinline__ float sigf(float x) {
    return __fdividef(1.0f, 1.0f + __expf(-x));
}
static __device__ __forceinline__ float tanh_f(float x) {
    float e = __expf(-2.0f * fabsf(x));
    float r = __fdividef(1.0f - e, 1.0f + e);
    return copysignf(r, x);
}
static __device__ __forceinline__ uint32_t bf2(float a, float b) {
    __nv_bfloat162 t = __floats2bfloat162_rn(a, b);
    return *reinterpret_cast<uint32_t*>(&t);
}
static __device__ __forceinline__ void split2(float x0, float x1,
                                              uint32_t& hi, uint32_t& lo) {
    uint32_t h = bf2(x0, x1);
    __nv_bfloat162 hv = *reinterpret_cast<__nv_bfloat162*>(&h);
    hi = h;
    lo = bf2(x0 - __low2float(hv), x1 - __high2float(hv));
}

__global__ void __launch_bounds__(NTHR, 1) __cluster_dims__(CLSZ, 1, 1)
lstm_mma_kernel(const float* __restrict__ state, const float* __restrict__ W_ih,
                const float* __restrict__ W_hh, const float* __restrict__ b_ih,
                const float* __restrict__ b_hh, const float* __restrict__ W_fc,
                const float* __restrict__ b_fc, float* __restrict__ out)
{
    extern __shared__ char smemc[];
    const uint32_t sb = s2u(smemc);
    const int tid = threadIdx.x, lane = tid & 31, warp = tid >> 5;
    const int wm = warp & 3;          // m-block: rows [wm*32, wm*32+32)
    const int jb = (warp >> 2) * 8;   // j-block: CTA-local j [jb, jb+8)

    uint32_t rank;
    asm("mov.u32 %0, %%cluster_ctarank;" : "=r"(rank));
    const int b0 = (blockIdx.x >> 2) * MB;

    // ---- W fill: tile row n = g*32 + jl  ->  gate row g*H + rank*32 + jl ----
    for (int e = tid; e < 128 * 192; e += NTHR) {
        int n = e & 127, k = e >> 7;
        int g = n >> 5, jl = n & 31;
        int grow = g * H_ + (int)rank * 32 + jl;
        float w = (k < 64) ? W_ih[grow * D_ + k] : W_hh[grow * H_ + (k - 64)];
        __nv_bfloat16 hi = __float2bfloat16(w);
        __nv_bfloat16 lo = __float2bfloat16(w - __bfloat162float(hi));
        uint32_t o = aoff(n, k);
        *(__nv_bfloat16*)(smemc + OFF_WHI + o) = hi;
        *(__nv_bfloat16*)(smemc + OFF_WLO + o) = lo;
    }
    // zero h region (k in [64,192) = bytes [16384,49152)) of A_hi/A_lo
    for (int e = tid; e < 8192; e += NTHR) {
        ((uint32_t*)(smemc + OFF_AHI + 16384))[e] = 0u;
        ((uint32_t*)(smemc + OFF_ALO + 16384))[e] = 0u;
    }

    // ---- per-thread bias (4 gates x 2 j) ----
    float bias[4][2];
#pragma unroll
    for (int g = 0; g < 4; g++)
#pragma unroll
        for (int jj = 0; jj < 2; jj++) {
            int grow = g * H_ + (int)rank * 32 + jb + (lane & 3) * 2 + jj;
            bias[g][jj] = b_ih[grow] + b_hh[grow];
        }

    // ---- ldmatrix lane geometry ----
    const int L = lane;
    const int arow = wm * 32 + ((L >> 3) & 1) * 8 + (L & 7);
    const uint32_t a_mask = (uint32_t)((arow & 7) << 4);
    const uint32_t a_k2   = (uint32_t)(((L >> 4) & 1) * 16);
    const uint32_t Abase  = sb + OFF_AHI
                          + (uint32_t)((arow >> 3) * 1024 + (arow & 7) * 128);
    const int wrow = ((L >> 4) & 1) * 32 + jb + (L & 7);
    const uint32_t w_mask = (uint32_t)((wrow & 7) << 4);
    const uint32_t w_k2   = (uint32_t)(((L >> 3) & 1) * 16);
    const uint32_t Wbase  = sb + OFF_WHI
                          + (uint32_t)((wrow >> 3) * 1024 + (wrow & 7) * 128);

    // ---- h store addresses (k = 64 + global j of this thread's j pair) ----
    const uint32_t hk = (uint32_t)(64 + (int)rank * 32 + jb + (lane & 3) * 2);
    const uint32_t h_mask  = (uint32_t)((lane >> 2) << 4);
    const uint32_t h_kpart = ((hk >> 6) << 14) + (((hk & 63) << 1) ^ h_mask);
    const uint32_t h_local = sb + OFF_AHI
                           + (uint32_t)(wm * 4 * 1024 + (lane >> 2) * 128) + h_kpart;
    uint32_t hb[CLSZ];
#pragma unroll
    for (int p = 0; p < CLSZ; p++) hb[p] = mapa_(h_local, (uint32_t)p);

    // ---- x geometry: thread -> (row = tid>>2, 16 dims at (tid&3)*16) ----
    const int xrow = tid >> 2, xd = (tid & 3) * 16;
    const uint32_t x_mask = (uint32_t)((xrow & 7) << 4);
    const uint32_t x_base = sb + OFF_AHI
                          + (uint32_t)((xrow >> 3) * 1024 + (xrow & 7) * 128);
    const uint32_t xc0 = x_base + (((uint32_t)(xd * 2)) ^ x_mask);
    const uint32_t xc1 = x_base + (((uint32_t)(xd * 2 + 16)) ^ x_mask);
    const float* xptr = state + (size_t)(b0 + xrow) * T_ * D_ + xd;

    // ---- x_0 into A ----
    {
        float xv[16];
#pragma unroll
        for (int i = 0; i < 4; i++) *(float4*)(xv + 4 * i) = *(const float4*)(xptr + 4 * i);
        uint32_t xh[8], xl[8];
#pragma unroll
        for (int p = 0; p < 8; p++) split2(xv[2 * p], xv[2 * p + 1], xh[p], xl[p]);
        stv4(xc0, xh); stv4(xc1, xh + 4);
        stv4(xc0 + TILE, xl); stv4(xc1 + TILE, xl + 4);
    }

    __syncthreads();
    cluster_sync_();

    float cst[8];     // [m*4 + half*2 + jj]
#pragma unroll
    for (int i = 0; i < 8; i++) cst[i] = 0.0f;

    for (int t = 0; t < T_; t++) {
        // prefetch x_{t+1} (completes under the GEMM)
        float xv[16];
        if (t < T_ - 1) {
            const float* xp = xptr + (size_t)(t + 1) * D_;
#pragma unroll
            for (int i = 0; i < 4; i++) *(float4*)(xv + 4 * i) = *(const float4*)(xp + 4 * i);
        }

        // ---- GEMM: acc[m][g] = bias; 3 combos over 12 k16 chunks ----
        float acc[2][4][4];
#pragma unroll
        for (int m = 0; m < 2; m++)
#pragma unroll
            for (int g = 0; g < 4; g++) {
                acc[m][g][0] = bias[g][0]; acc[m][g][1] = bias[g][1];
                acc[m][g][2] = bias[g][0]; acc[m][g][3] = bias[g][1];
            }

#pragma unroll
        for (int kt = 0; kt < 12; kt++) {
            const int k = kt * 16;
            const uint32_t kc = (uint32_t)((k >> 6) * 16384);
            const uint32_t K2 = (uint32_t)((k & 63) * 2);
            const uint32_t ao = kc + ((K2 + a_k2) ^ a_mask);
            const uint32_t wo = kc + ((K2 + w_k2) ^ w_mask);
            uint32_t Ah[2][4], Al[2][4], Wh[2][4], Wl[2][4];
            ldm4(Ah[0], Abase + ao);
            ldm4(Ah[1], Abase + ao + 2048);
            ldm4(Al[0], Abase + ao + TILE);
            ldm4(Al[1], Abase + ao + TILE + 2048);
            ldm4(Wh[0], Wbase + wo);
            ldm4(Wh[1], Wbase + wo + 8192);
            ldm4(Wl[0], Wbase + wo + TILE);
            ldm4(Wl[1], Wbase + wo + TILE + 8192);
#pragma unroll
            for (int m = 0; m < 2; m++)
#pragma unroll
                for (int g = 0; g < 4; g++) {
                    const uint32_t* bh = &Wh[g >> 1][(g & 1) * 2];
                    const uint32_t* bl = &Wl[g >> 1][(g & 1) * 2];
                    mma_bf16(acc[m][g], Ah[m], bh);
                    mma_bf16(acc[m][g], Al[m], bh);
                    mma_bf16(acc[m][g], Ah[m], bl);
                }
        }

        // ---- activations (8 cells: 2m x 2half x 2j) ----
        uint32_t hp[4], lp[4];   // per (m,half): packed j-pair hi/lo
#pragma unroll
        for (int m = 0; m < 2; m++)
#pragma unroll
            for (int hf = 0; hf < 2; hf++) {
                float hvj[2];
#pragma unroll
                for (int jj = 0; jj < 2; jj++) {
                    int q = hf * 2 + jj;
                    float gi = acc[m][0][q], gf = acc[m][1][q];
                    float gg = acc[m][2][q], go = acc[m][3][q];
                    int ci = m * 4 + hf * 2 + jj;
                    float cn = sigf(gf) * cst[ci] + sigf(gi) * tanh_f(gg);
                    cst[ci] = cn;
                    hvj[jj] = sigf(go) * tanh_f(cn);
                }
                split2(hvj[0], hvj[1], hp[m * 2 + hf], lp[m * 2 + hf]);
            }

        cluster_sync_();   // all CTAs done reading A

        // ---- h to all 4 CTAs' A tiles; x_{t+1} locally ----
#pragma unroll
        for (int p = 0; p < CLSZ; p++)
#pragma unroll
            for (int mh = 0; mh < 4; mh++) {
                stc32(hb[p] + (uint32_t)(mh * 1024), hp[mh]);
                stc32(hb[p] + (uint32_t)(mh * 1024) + TILE, lp[mh]);
            }
        if (t < T_ - 1) {
            uint32_t xh[8], xl[8];
#pragma unroll
            for (int p = 0; p < 8; p++) split2(xv[2 * p], xv[2 * p + 1], xh[p], xl[p]);
            stv4(xc0, xh); stv4(xc1, xh + 4);
            stv4(xc0 + TILE, xl); stv4(xc1 + TILE, xl + 4);
        }

        cluster_sync_();   // stores visible before next GEMM
    }

    // ---- FC: out = tanh(h @ W_fc^T + b_fc); rows rank*32+lane, a = warp ----
    if (warp < A_) {
        int r = (int)rank * 32 + lane;
        float acc = b_fc[warp];
        const float* wf = W_fc + warp * H_;
#pragma unroll 8
        for (int j = 0; j < H_; j++) {
            uint32_t o = aoff(r, 64 + j);
            float h = __bfloat162float(*(const __nv_bfloat16*)(smemc + OFF_AHI + o))
                    + __bfloat162float(*(const __nv_bfloat16*)(smemc + OFF_ALO + o));
            acc += h * wf[j];
        }
        out[(size_t)(b0 + r) * A_ + warp] = tanhf(acc);
    }
}

extern "C" void kernel_launch(void* const* d_in, const int* in_sizes, int n_in,
                              void* d_out, int out_size) {
    (void)in_sizes; (void)n_in; (void)out_size;
    cudaFuncSetAttribute(lstm_mma_kernel,
                         cudaFuncAttributeMaxDynamicSharedMemorySize, SMEM_BYTES);
    lstm_mma_kernel<<<(B_ / MB) * CLSZ, NTHR, SMEM_BYTES>>>(
        (const float*)d_in[0], (const float*)d_in[1], (const float*)d_in[2],
        (const float*)d_in[3], (const float*)d_in[4], (const float*)d_in[5],
        (const float*)d_in[6], (float*)d_out);
}

// round 11
// speedup vs baseline: 3.9929x; 1.1660x over previous
#include <cuda_runtime.h>
#include <cuda_fp16.h>
#include <cstdint>

#define B_   4096
#define T_   512
#define D_   64
#define H_   128
#define A_   8

#define CLSZ 4
#define MB   128     // batch rows per cluster (M)
#define NTHR 512     // 16 warps: warp tile 32m x 32n

// smem: three [128 x 192] fp16 tiles, SW128 blocked atoms (16 atomrows x 3 atomcols)
//   A_hi, A_lo (activation split), W_hi (weights, fp16; no W_lo combo)
#define TILE     49152
#define OFF_AHI  0
#define OFF_ALO  49152
#define OFF_WHI  98304
#define SMEM_BYTES 147456

// ---------------- helpers ----------------
static __device__ __forceinline__ uint32_t s2u(const void* p) {
    uint32_t a;
    asm("{ .reg .u64 t; cvta.to.shared.u64 t, %1; cvt.u32.u64 %0, t; }" : "=r"(a) : "l"(p));
    return a;
}
static __device__ __forceinline__ void cluster_sync_() {
    asm volatile("barrier.cluster.arrive.aligned;" ::: "memory");
    asm volatile("barrier.cluster.wait.aligned;" ::: "memory");
}
static __device__ __forceinline__ void cluster_arrive_() {
    asm volatile("barrier.cluster.arrive.aligned;" ::: "memory");
}
static __device__ __forceinline__ void cluster_wait_() {
    asm volatile("barrier.cluster.wait.aligned;" ::: "memory");
}
static __device__ __forceinline__ uint32_t mapa_(uint32_t a, uint32_t r) {
    uint32_t d;
    asm("mapa.shared::cluster.u32 %0, %1, %2;" : "=r"(d) : "r"(a), "r"(r));
    return d;
}
static __device__ __forceinline__ void ldm4(uint32_t* r, uint32_t addr) {
    asm volatile("ldmatrix.sync.aligned.m8n8.x4.shared.b16 {%0,%1,%2,%3}, [%4];"
                 : "=r"(r[0]), "=r"(r[1]), "=r"(r[2]), "=r"(r[3]) : "r"(addr));
}
static __device__ __forceinline__ void mma_f16(float* d, const uint32_t* a,
                                               const uint32_t* b) {
    asm volatile("mma.sync.aligned.m16n8k16.row.col.f32.f16.f16.f32 "
                 "{%0,%1,%2,%3}, {%4,%5,%6,%7}, {%8,%9}, {%0,%1,%2,%3};"
                 : "+f"(d[0]), "+f"(d[1]), "+f"(d[2]), "+f"(d[3])
                 : "r"(a[0]), "r"(a[1]), "r"(a[2]), "r"(a[3]), "r"(b[0]), "r"(b[1]));
}
static __device__ __forceinline__ void stc32(uint32_t a, uint32_t v) {
    asm volatile("st.shared::cluster.b32 [%0], %1;" :: "r"(a), "r"(v) : "memory");
}
static __device__ __forceinline__ void stv4(uint32_t a, const uint32_t* v) {
    asm volatile("st.shared.v4.b32 [%0], {%1,%2,%3,%4};"
                 :: "r"(a), "r"(v[0]), "r"(v[1]), "r"(v[2]), "r"(v[3]) : "memory");
}
// byte offset of (row, k) in a [128 x 192] fp16 blocked-SW128 tile (init/FC path)
static __device__ __forceinline__ uint32_t aoff(int row, int k) {
    uint32_t b = (uint32_t)(((row >> 3) + (k >> 6) * 16) * 1024
                            + (row & 7) * 128 + (k & 63) * 2);
    return b ^ ((b >> 3) & 0x70);
}
// fast overflow-safe sigmoid / tanh (MUFU ex2/rcp, ~1e-6)
static __device__ __forceinline__ float sigf(float x) {
    return __fdividef(1.0f, 1.0f + __expf(-x));
}
static __device__ __forceinline__ float tanh_f(float x) {
    float e = __expf(-2.0f * fabsf(x));
    float r = __fdividef(1.0f - e, 1.0f + e);
    return copysignf(r, x);
}
static __device__ __forceinline__ uint32_t hf2(float a, float b) {
    __half2 t = __floats2half2_rn(a, b);
    return *reinterpret_cast<uint32_t*>(&t);
}
static __device__ __forceinline__ void split2(float x0, float x1,
                                              uint32_t& hi, uint32_t& lo) {
    uint32_t h = hf2(x0, x1);
    __half2 hv = *reinterpret_cast<__half2*>(&h);
    hi = h;
    lo = hf2(x0 - __low2float(hv), x1 - __high2float(hv));
}

__global__ void __launch_bounds__(NTHR, 1) __cluster_dims__(CLSZ, 1, 1)
lstm_mma_kernel(const float* __restrict__ state, const float* __restrict__ W_ih,
                const float* __restrict__ W_hh, const float* __restrict__ b_ih,
                const float* __restrict__ b_hh, const float* __restrict__ W_fc,
                const float* __restrict__ b_fc, float* __restrict__ out)
{
    extern __shared__ char smemc[];
    const uint32_t sb = s2u(smemc);
    const int tid = threadIdx.x, lane = tid & 31, warp = tid >> 5;
    const int wm = warp & 3;          // m-block: rows [wm*32, wm*32+32)
    const int jb = (warp >> 2) * 8;   // j-block: CTA-local j [jb, jb+8)

    uint32_t rank;
    asm("mov.u32 %0, %%cluster_ctarank;" : "=r"(rank));
    const int b0 = (blockIdx.x >> 2) * MB;

    // ---- W fill (fp16, no lo): tile row n = g*32 + jl -> gate row g*H + rank*32 + jl ----
    for (int e = tid; e < 128 * 192; e += NTHR) {
        int n = e & 127, k = e >> 7;
        int g = n >> 5, jl = n & 31;
        int grow = g * H_ + (int)rank * 32 + jl;
        float w = (k < 64) ? W_ih[grow * D_ + k] : W_hh[grow * H_ + (k - 64)];
        *(__half*)(smemc + OFF_WHI + aoff(n, k)) = __float2half_rn(w);
    }
    // zero h region (k in [64,192) = bytes [16384,49152)) of A_hi/A_lo
    for (int e = tid; e < 8192; e += NTHR) {
        ((uint32_t*)(smemc + OFF_AHI + 16384))[e] = 0u;
        ((uint32_t*)(smemc + OFF_ALO + 16384))[e] = 0u;
    }

    // ---- per-thread bias (4 gates x 2 j) ----
    float bias[4][2];
#pragma unroll
    for (int g = 0; g < 4; g++)
#pragma unroll
        for (int jj = 0; jj < 2; jj++) {
            int grow = g * H_ + (int)rank * 32 + jb + (lane & 3) * 2 + jj;
            bias[g][jj] = b_ih[grow] + b_hh[grow];
        }

    // ---- ldmatrix lane geometry ----
    const int L = lane;
    const int arow = wm * 32 + ((L >> 3) & 1) * 8 + (L & 7);
    const uint32_t a_mask = (uint32_t)((arow & 7) << 4);
    const uint32_t a_k2   = (uint32_t)(((L >> 4) & 1) * 16);
    const uint32_t Abase  = sb + OFF_AHI
                          + (uint32_t)((arow >> 3) * 1024 + (arow & 7) * 128);
    const int wrow = ((L >> 4) & 1) * 32 + jb + (L & 7);
    const uint32_t w_mask = (uint32_t)((wrow & 7) << 4);
    const uint32_t w_k2   = (uint32_t)(((L >> 3) & 1) * 16);
    const uint32_t Wbase  = sb + OFF_WHI
                          + (uint32_t)((wrow >> 3) * 1024 + (wrow & 7) * 128);

    // ---- h store addresses (k = 64 + global j of this thread's j pair) ----
    const uint32_t hk = (uint32_t)(64 + (int)rank * 32 + jb + (lane & 3) * 2);
    const uint32_t h_mask  = (uint32_t)((lane >> 2) << 4);
    const uint32_t h_kpart = ((hk >> 6) << 14) + (((hk & 63) << 1) ^ h_mask);
    const uint32_t h_local = sb + OFF_AHI
                           + (uint32_t)(wm * 4 * 1024 + (lane >> 2) * 128) + h_kpart;
    uint32_t hb[CLSZ];
#pragma unroll
    for (int p = 0; p < CLSZ; p++) hb[p] = mapa_(h_local, (uint32_t)p);

    // ---- x geometry: thread -> (row = tid>>2, 16 dims at (tid&3)*16) ----
    const int xrow = tid >> 2, xd = (tid & 3) * 16;
    const uint32_t x_mask = (uint32_t)((xrow & 7) << 4);
    const uint32_t x_base = sb + OFF_AHI
                          + (uint32_t)((xrow >> 3) * 1024 + (xrow & 7) * 128);
    const uint32_t xc0 = x_base + (((uint32_t)(xd * 2)) ^ x_mask);
    const uint32_t xc1 = x_base + (((uint32_t)(xd * 2 + 16)) ^ x_mask);
    const float* xptr = state + (size_t)(b0 + xrow) * T_ * D_ + xd;

    // ---- x_0 into A ----
    {
        float xv[16];
#pragma unroll
        for (int i = 0; i < 4; i++) *(float4*)(xv + 4 * i) = *(const float4*)(xptr + 4 * i);
        uint32_t xh[8], xl[8];
#pragma unroll
        for (int p = 0; p < 8; p++) split2(xv[2 * p], xv[2 * p + 1], xh[p], xl[p]);
        stv4(xc0, xh); stv4(xc1, xh + 4);
        stv4(xc0 + TILE, xl); stv4(xc1 + TILE, xl + 4);
    }

    __syncthreads();
    cluster_sync_();

    float cst[8];     // [m*4 + half*2 + jj]
#pragma unroll
    for (int i = 0; i < 8; i++) cst[i] = 0.0f;

    for (int t = 0; t < T_; t++) {
        // prefetch x_{t+1} (completes under the GEMM)
        float xv[16];
        if (t < T_ - 1) {
            const float* xp = xptr + (size_t)(t + 1) * D_;
#pragma unroll
            for (int i = 0; i < 4; i++) *(float4*)(xv + 4 * i) = *(const float4*)(xp + 4 * i);
        }

        // ---- GEMM: acc[m][g] = bias; 2 combos (Ah*W + Al*W) over 12 k16 chunks ----
        float acc[2][4][4];
#pragma unroll
        for (int m = 0; m < 2; m++)
#pragma unroll
            for (int g = 0; g < 4; g++) {
                acc[m][g][0] = bias[g][0]; acc[m][g][1] = bias[g][1];
                acc[m][g][2] = bias[g][0]; acc[m][g][3] = bias[g][1];
            }

#pragma unroll
        for (int kt = 0; kt < 12; kt++) {
            const int k = kt * 16;
            const uint32_t kc = (uint32_t)((k >> 6) * 16384);
            const uint32_t K2 = (uint32_t)((k & 63) * 2);
            const uint32_t ao = kc + ((K2 + a_k2) ^ a_mask);
            const uint32_t wo = kc + ((K2 + w_k2) ^ w_mask);
            uint32_t Ah[2][4], Al[2][4], Wh[2][4];
            ldm4(Ah[0], Abase + ao);
            ldm4(Ah[1], Abase + ao + 2048);
            ldm4(Al[0], Abase + ao + TILE);
            ldm4(Al[1], Abase + ao + TILE + 2048);
            ldm4(Wh[0], Wbase + wo);
            ldm4(Wh[1], Wbase + wo + 8192);
#pragma unroll
            for (int m = 0; m < 2; m++)
#pragma unroll
                for (int g = 0; g < 4; g++) {
                    const uint32_t* bh = &Wh[g >> 1][(g & 1) * 2];
                    mma_f16(acc[m][g], Ah[m], bh);
                    mma_f16(acc[m][g], Al[m], bh);
                }
        }

        cluster_arrive_();   // my A-reads are done; overlap epilogue with peer skew

        // ---- activations (8 cells: 2m x 2half x 2j) ----
        uint32_t hp[4], lp[4];   // per (m,half): packed j-pair hi/lo
#pragma unroll
        for (int m = 0; m < 2; m++)
#pragma unroll
            for (int hf = 0; hf < 2; hf++) {
                float hvj[2];
#pragma unroll
                for (int jj = 0; jj < 2; jj++) {
                    int q = hf * 2 + jj;
                    float gi = acc[m][0][q], gf = acc[m][1][q];
                    float gg = acc[m][2][q], go = acc[m][3][q];
                    int ci = m * 4 + hf * 2 + jj;
                    float cn = sigf(gf) * cst[ci] + sigf(gi) * tanh_f(gg);
                    cst[ci] = cn;
                    hvj[jj] = sigf(go) * tanh_f(cn);
                }
                split2(hvj[0], hvj[1], hp[m * 2 + hf], lp[m * 2 + hf]);
            }

        cluster_wait_();   // all CTAs done reading A

        // ---- h to all 4 CTAs' A tiles; x_{t+1} locally ----
#pragma unroll
        for (int p = 0; p < CLSZ; p++)
#pragma unroll
            for (int mh = 0; mh < 4; mh++) {
                stc32(hb[p] + (uint32_t)(mh * 1024), hp[mh]);
                stc32(hb[p] + (uint32_t)(mh * 1024) + TILE, lp[mh]);
            }
        if (t < T_ - 1) {
            uint32_t xh[8], xl[8];
#pragma unroll
            for (int p = 0; p < 8; p++) split2(xv[2 * p], xv[2 * p + 1], xh[p], xl[p]);
            stv4(xc0, xh); stv4(xc1, xh + 4);
            stv4(xc0 + TILE, xl); stv4(xc1 + TILE, xl + 4);
        }

        cluster_sync_();   // stores visible before next GEMM
    }

    // ---- FC: out = tanh(h @ W_fc^T + b_fc); rows rank*32+lane, a = warp ----
    if (warp < A_) {
        int r = (int)rank * 32 + lane;
        float acc = b_fc[warp];
        const float* wf = W_fc + warp * H_;
#pragma unroll 8
        for (int j = 0; j < H_; j++) {
            uint32_t o = aoff(r, 64 + j);
            float h = __half2float(*(const __half*)(smemc + OFF_AHI + o))
                    + __half2float(*(const __half*)(smemc + OFF_ALO + o));
            acc += h * wf[j];
        }
        out[(size_t)(b0 + r) * A_ + warp] = tanhf(acc);
    }
}

extern "C" void kernel_launch(void* const* d_in, const int* in_sizes, int n_in,
                              void* d_out, int out_size) {
    (void)in_sizes; (void)n_in; (void)out_size;
    cudaFuncSetAttribute(lstm_mma_kernel,
                         cudaFuncAttributeMaxDynamicSharedMemorySize, SMEM_BYTES);
    lstm_mma_kernel<<<(B_ / MB) * CLSZ, NTHR, SMEM_BYTES>>>(
        (const float*)d_in[0], (const float*)d_in[1], (const float*)d_in[2],
        (const float*)d_in[3], (const float*)d_in[4], (const float*)d_in[5],
        (const float*)d_in[6], (float*)d_out);
}

// round 15
// speedup vs baseline: 6.4103x; 1.6054x over previous
#include <cuda_runtime.h>
#include <cuda_fp16.h>
#include <cstdint>

#define B_   4096
#define T_   512
#define D_   64
#define H_   128
#define A_   8

#define CLSZ 4
#define MB   128     // batch rows per cluster (M)
#define NTHR 512     // 16 warps: warp tile 32m x 32n

// smem: two [128 x 192] fp16 tiles, SW128 blocked atoms (16 atomrows x 3 atomcols)
//   A (activations, in-place h/x update), W (fp16 weights)
#define TILE     49152
#define OFF_A    0
#define OFF_W    49152
#define SMEM_BYTES 98304

// ---------------- helpers ----------------
static __device__ __forceinline__ uint32_t s2u(const void* p) {
    uint32_t a;
    asm("{ .reg .u64 t; cvta.to.shared.u64 t, %1; cvt.u32.u64 %0, t; }" : "=r"(a) : "l"(p));
    return a;
}
static __device__ __forceinline__ void cluster_sync_() {
    asm volatile("barrier.cluster.arrive.aligned;" ::: "memory");
    asm volatile("barrier.cluster.wait.aligned;" ::: "memory");
}
static __device__ __forceinline__ void cluster_arrive_() {
    asm volatile("barrier.cluster.arrive.aligned;" ::: "memory");
}
static __device__ __forceinline__ void cluster_wait_() {
    asm volatile("barrier.cluster.wait.aligned;" ::: "memory");
}
static __device__ __forceinline__ uint32_t mapa_(uint32_t a, uint32_t r) {
    uint32_t d;
    asm("mapa.shared::cluster.u32 %0, %1, %2;" : "=r"(d) : "r"(a), "r"(r));
    return d;
}
static __device__ __forceinline__ void ldm4(uint32_t* r, uint32_t addr) {
    asm volatile("ldmatrix.sync.aligned.m8n8.x4.shared.b16 {%0,%1,%2,%3}, [%4];"
                 : "=r"(r[0]), "=r"(r[1]), "=r"(r[2]), "=r"(r[3]) : "r"(addr));
}
static __device__ __forceinline__ void mma_f16(float* d, const uint32_t* a,
                                               const uint32_t* b) {
    asm volatile("mma.sync.aligned.m16n8k16.row.col.f32.f16.f16.f32 "
                 "{%0,%1,%2,%3}, {%4,%5,%6,%7}, {%8,%9}, {%0,%1,%2,%3};"
                 : "+f"(d[0]), "+f"(d[1]), "+f"(d[2]), "+f"(d[3])
                 : "r"(a[0]), "r"(a[1]), "r"(a[2]), "r"(a[3]), "r"(b[0]), "r"(b[1]));
}
static __device__ __forceinline__ void stc32(uint32_t a, uint32_t v) {
    asm volatile("st.shared::cluster.b32 [%0], %1;" :: "r"(a), "r"(v) : "memory");
}
static __device__ __forceinline__ void stv4(uint32_t a, const uint32_t* v) {
    asm volatile("st.shared.v4.b32 [%0], {%1,%2,%3,%4};"
                 :: "r"(a), "r"(v[0]), "r"(v[1]), "r"(v[2]), "r"(v[3]) : "memory");
}
// byte offset of (row, k) in a [128 x 192] fp16 blocked-SW128 tile (init/FC path)
static __device__ __forceinline__ uint32_t aoff(int row, int k) {
    uint32_t b = (uint32_t)(((row >> 3) + (k >> 6) * 16) * 1024
                            + (row & 7) * 128 + (k & 63) * 2);
    return b ^ ((b >> 3) & 0x70);
}
// MUFU tanh-based activations
static __device__ __forceinline__ float tanht(float x) {
    float r;
    asm("tanh.approx.f32 %0, %1;" : "=f"(r) : "f"(x));
    return r;
}
static __device__ __forceinline__ float sigt(float x) {
    return fmaf(0.5f, tanht(0.5f * x), 0.5f);
}
static __device__ __forceinline__ uint32_t hf2(float a, float b) {
    __half2 t = __floats2half2_rn(a, b);
    return *reinterpret_cast<uint32_t*>(&t);
}

__global__ void __launch_bounds__(NTHR, 1) __cluster_dims__(CLSZ, 1, 1)
lstm_mma_kernel(const float* __restrict__ state, const float* __restrict__ W_ih,
                const float* __restrict__ W_hh, const float* __restrict__ b_ih,
                const float* __restrict__ b_hh, const float* __restrict__ W_fc,
                const float* __restrict__ b_fc, float* __restrict__ out)
{
    extern __shared__ char smemc[];
    const uint32_t sb = s2u(smemc);
    const int tid = threadIdx.x, lane = tid & 31, warp = tid >> 5;
    const int wm = warp & 3;          // m-block: rows [wm*32, wm*32+32)
    const int jb = (warp >> 2) * 8;   // j-block: CTA-local j [jb, jb+8)

    uint32_t rank;
    asm("mov.u32 %0, %%cluster_ctarank;" : "=r"(rank));
    const int b0 = (blockIdx.x >> 2) * MB;

    // ---- W fill (fp16): tile row n = g*32 + jl -> gate row g*H + rank*32 + jl ----
    for (int e = tid; e < 128 * 192; e += NTHR) {
        int n = e & 127, k = e >> 7;
        int g = n >> 5, jl = n & 31;
        int grow = g * H_ + (int)rank * 32 + jl;
        float w = (k < 64) ? W_ih[grow * D_ + k] : W_hh[grow * H_ + (k - 64)];
        *(__half*)(smemc + OFF_W + aoff(n, k)) = __float2half_rn(w);
    }
    // zero h region of A (k in [64,192) = bytes [16384,49152))
    for (int e = tid; e < 8192; e += NTHR)
        ((uint32_t*)(smemc + OFF_A + 16384))[e] = 0u;

    // ---- per-thread bias (4 gates x 2 j) ----
    float bias[4][2];
#pragma unroll
    for (int g = 0; g < 4; g++)
#pragma unroll
        for (int jj = 0; jj < 2; jj++) {
            int grow = g * H_ + (int)rank * 32 + jb + (lane & 3) * 2 + jj;
            bias[g][jj] = b_ih[grow] + b_hh[grow];
        }

    // ---- ldmatrix lane geometry ----
    const int L = lane;
    const int arow = wm * 32 + ((L >> 3) & 1) * 8 + (L & 7);
    const uint32_t a_mask = (uint32_t)((arow & 7) << 4);
    const uint32_t a_k2   = (uint32_t)(((L >> 4) & 1) * 16);
    const uint32_t Abase  = sb + OFF_A
                          + (uint32_t)((arow >> 3) * 1024 + (arow & 7) * 128);
    const int wrow = ((L >> 4) & 1) * 32 + jb + (L & 7);
    const uint32_t w_mask = (uint32_t)((wrow & 7) << 4);
    const uint32_t w_k2   = (uint32_t)(((L >> 3) & 1) * 16);
    const uint32_t Wbase  = sb + OFF_W
                          + (uint32_t)((wrow >> 3) * 1024 + (wrow & 7) * 128);

    // ---- h store addresses (k = 64 + global j of this thread's j pair) ----
    const uint32_t hk = (uint32_t)(64 + (int)rank * 32 + jb + (lane & 3) * 2);
    const uint32_t h_mask  = (uint32_t)((lane >> 2) << 4);
    const uint32_t h_kpart = ((hk >> 6) << 14) + (((hk & 63) << 1) ^ h_mask);
    const uint32_t h_local = sb + OFF_A
                           + (uint32_t)(wm * 4 * 1024 + (lane >> 2) * 128) + h_kpart;
    uint32_t hb[CLSZ];
#pragma unroll
    for (int p = 0; p < CLSZ; p++) hb[p] = mapa_(h_local, (uint32_t)p);

    // ---- x geometry: thread -> (row = tid>>2, 16 dims at (tid&3)*16) ----
    const int xrow = tid >> 2, xd = (tid & 3) * 16;
    const uint32_t x_mask = (uint32_t)((xrow & 7) << 4);
    const uint32_t x_base = sb + OFF_A
                          + (uint32_t)((xrow >> 3) * 1024 + (xrow & 7) * 128);
    const uint32_t xc0 = x_base + (((uint32_t)(xd * 2)) ^ x_mask);
    const uint32_t xc1 = x_base + (((uint32_t)(xd * 2 + 16)) ^ x_mask);
    const float* xptr = state + (size_t)(b0 + xrow) * T_ * D_ + xd;

    // ---- x_0 into A ----
    {
        float xv[16];
#pragma unroll
        for (int i = 0; i < 4; i++) *(float4*)(xv + 4 * i) = *(const float4*)(xptr + 4 * i);
        uint32_t xh[8];
#pragma unroll
        for (int p = 0; p < 8; p++) xh[p] = hf2(xv[2 * p], xv[2 * p + 1]);
        stv4(xc0, xh); stv4(xc1, xh + 4);
    }

    __syncthreads();
    cluster_sync_();

    float cst[8];     // [m*4 + half*2 + jj]
#pragma unroll
    for (int i = 0; i < 8; i++) cst[i] = 0.0f;

    for (int t = 0; t < T_; t++) {
        // prefetch x_{t+1} (completes under the GEMM)
        float xv[16];
        if (t < T_ - 1) {
            const float* xp = xptr + (size_t)(t + 1) * D_;
#pragma unroll
            for (int i = 0; i < 4; i++) *(float4*)(xv + 4 * i) = *(const float4*)(xp + 4 * i);
        }

        // ---- GEMM: acc[m][g] = bias; single fp16 combo over 12 k16 chunks ----
        float acc[2][4][4];
#pragma unroll
        for (int m = 0; m < 2; m++)
#pragma unroll
            for (int g = 0; g < 4; g++) {
                acc[m][g][0] = bias[g][0]; acc[m][g][1] = bias[g][1];
                acc[m][g][2] = bias[g][0]; acc[m][g][3] = bias[g][1];
            }

#pragma unroll
        for (int kt = 0; kt < 12; kt++) {
            const int k = kt * 16;
            const uint32_t kc = (uint32_t)((k >> 6) * 16384);
            const uint32_t K2 = (uint32_t)((k & 63) * 2);
            const uint32_t ao = kc + ((K2 + a_k2) ^ a_mask);
            const uint32_t wo = kc + ((K2 + w_k2) ^ w_mask);
            uint32_t Ah[2][4], Wh[2][4];
            ldm4(Ah[0], Abase + ao);
            ldm4(Ah[1], Abase + ao + 2048);
            ldm4(Wh[0], Wbase + wo);
            ldm4(Wh[1], Wbase + wo + 8192);
#pragma unroll
            for (int m = 0; m < 2; m++)
#pragma unroll
                for (int g = 0; g < 4; g++)
                    mma_f16(acc[m][g], Ah[m], &Wh[g >> 1][(g & 1) * 2]);
        }

        cluster_arrive_();   // my A-reads are done; overlap epilogue with peer skew

        // ---- activations (8 cells: 2m x 2half x 2j), tanh.approx ----
        uint32_t hp[4];   // per (m,half): packed j-pair
#pragma unroll
        for (int m = 0; m < 2; m++)
#pragma unroll
            for (int hf = 0; hf < 2; hf++) {
                float hvj[2];
#pragma unroll
                for (int jj = 0; jj < 2; jj++) {
                    int q = hf * 2 + jj;
                    float gi = acc[m][0][q], gf = acc[m][1][q];
                    float gg = acc[m][2][q], go = acc[m][3][q];
                    int ci = m * 4 + hf * 2 + jj;
                    float cn = sigt(gf) * cst[ci] + sigt(gi) * tanht(gg);
                    cst[ci] = cn;
                    hvj[jj] = sigt(go) * tanht(cn);
                }
                hp[m * 2 + hf] = hf2(hvj[0], hvj[1]);
            }

        cluster_wait_();   // all CTAs done reading A

        // ---- h to all 4 CTAs' A tiles (in place); x_{t+1} locally ----
#pragma unroll
        for (int p = 0; p < CLSZ; p++)
#pragma unroll
            for (int mh = 0; mh < 4; mh++)
                stc32(hb[p] + (uint32_t)(mh * 1024), hp[mh]);
        if (t < T_ - 1) {
            uint32_t xh[8];
#pragma unroll
            for (int p = 0; p < 8; p++) xh[p] = hf2(xv[2 * p], xv[2 * p + 1]);
            stv4(xc0, xh); stv4(xc1, xh + 4);
        }

        cluster_sync_();   // stores visible before next GEMM
    }

    // ---- FC: out = tanh(h @ W_fc^T + b_fc); rows rank*32+lane, a = warp ----
    if (warp < A_) {
        int r = (int)rank * 32 + lane;
        float acc = b_fc[warp];
        const float* wf = W_fc + warp * H_;
#pragma unroll 8
        for (int j = 0; j < H_; j++) {
            float h = __half2float(*(const __half*)(smemc + OFF_A + aoff(r, 64 + j)));
            acc += h * wf[j];
        }
        out[(size_t)(b0 + r) * A_ + warp] = tanhf(acc);
    }
}

extern "C" void kernel_launch(void* const* d_in, const int* in_sizes, int n_in,
                              void* d_out, int out_size) {
    (void)in_sizes; (void)n_in; (void)out_size;
    cudaFuncSetAttribute(lstm_mma_kernel,
                         cudaFuncAttributeMaxDynamicSharedMemorySize, SMEM_BYTES);
    lstm_mma_kernel<<<(B_ / MB) * CLSZ, NTHR, SMEM_BYTES>>>(
        (const float*)d_in[0], (const float*)d_in[1], (const float*)d_in[2],
        (const float*)d_in[3], (const float*)d_in[4], (const float*)d_in[5],
        (const float*)d_in[6], (float*)d_out);
}

// round 17
// speedup vs baseline: 7.9323x; 1.2374x over previous
#include <cuda_runtime.h>
#include <cuda_fp16.h>
#include <cstdint>

#define B_   4096
#define T_   512
#define D_   64
#define H_   128
#define A_   8

#define CLSZ 4
#define MB   128     // batch rows per cluster (M)
#define NTHR 512     // 16 warps: warp tile 32m x 32n

// smem: three [128 x 192] fp16 tiles, SW128 blocked atoms (16 atomrows x 3 atomcols)
//   A0, A1 (double-buffered activations), W (fp16 weights)
#define TILE     49152
#define OFF_A0   0
#define OFF_A1   49152
#define OFF_W    98304
#define SMEM_BYTES 147456

// ---------------- helpers ----------------
static __device__ __forceinline__ uint32_t s2u(const void* p) {
    uint32_t a;
    asm("{ .reg .u64 t; cvta.to.shared.u64 t, %1; cvt.u32.u64 %0, t; }" : "=r"(a) : "l"(p));
    return a;
}
static __device__ __forceinline__ void cluster_sync_() {
    asm volatile("barrier.cluster.arrive.aligned;" ::: "memory");
    asm volatile("barrier.cluster.wait.aligned;" ::: "memory");
}
static __device__ __forceinline__ uint32_t mapa_(uint32_t a, uint32_t r) {
    uint32_t d;
    asm("mapa.shared::cluster.u32 %0, %1, %2;" : "=r"(d) : "r"(a), "r"(r));
    return d;
}
static __device__ __forceinline__ void ldm4(uint32_t* r, uint32_t addr) {
    asm volatile("ldmatrix.sync.aligned.m8n8.x4.shared.b16 {%0,%1,%2,%3}, [%4];"
                 : "=r"(r[0]), "=r"(r[1]), "=r"(r[2]), "=r"(r[3]) : "r"(addr));
}
static __device__ __forceinline__ void mma_f16(float* d, const uint32_t* a,
                                               const uint32_t* b) {
    asm volatile("mma.sync.aligned.m16n8k16.row.col.f32.f16.f16.f32 "
                 "{%0,%1,%2,%3}, {%4,%5,%6,%7}, {%8,%9}, {%0,%1,%2,%3};"
                 : "+f"(d[0]), "+f"(d[1]), "+f"(d[2]), "+f"(d[3])
                 : "r"(a[0]), "r"(a[1]), "r"(a[2]), "r"(a[3]), "r"(b[0]), "r"(b[1]));
}
static __device__ __forceinline__ void stc32(uint32_t a, uint32_t v) {
    asm volatile("st.shared::cluster.b32 [%0], %1;" :: "r"(a), "r"(v) : "memory");
}
static __device__ __forceinline__ void stv4(uint32_t a, const uint32_t* v) {
    asm volatile("st.shared.v4.b32 [%0], {%1,%2,%3,%4};"
                 :: "r"(a), "r"(v[0]), "r"(v[1]), "r"(v[2]), "r"(v[3]) : "memory");
}
// byte offset of (row, k) in a [128 x 192] fp16 blocked-SW128 tile (init/FC path)
static __device__ __forceinline__ uint32_t aoff(int row, int k) {
    uint32_t b = (uint32_t)(((row >> 3) + (k >> 6) * 16) * 1024
                            + (row & 7) * 128 + (k & 63) * 2);
    return b ^ ((b >> 3) & 0x70);
}
// MUFU tanh-based activations
static __device__ __forceinline__ float tanht(float x) {
    float r;
    asm("tanh.approx.f32 %0, %1;" : "=f"(r) : "f"(x));
    return r;
}
static __device__ __forceinline__ float sigt(float x) {
    return fmaf(0.5f, tanht(0.5f * x), 0.5f);
}
static __device__ __forceinline__ uint32_t hf2(float a, float b) {
    __half2 t = __floats2half2_rn(a, b);
    return *reinterpret_cast<uint32_t*>(&t);
}

__global__ void __launch_bounds__(NTHR, 1) __cluster_dims__(CLSZ, 1, 1)
lstm_mma_kernel(const float* __restrict__ state, const float* __restrict__ W_ih,
                const float* __restrict__ W_hh, const float* __restrict__ b_ih,
                const float* __restrict__ b_hh, const float* __restrict__ W_fc,
                const float* __restrict__ b_fc, float* __restrict__ out)
{
    extern __shared__ char smemc[];
    const uint32_t sb = s2u(smemc);
    const int tid = threadIdx.x, lane = tid & 31, warp = tid >> 5;
    const int wm = warp & 3;          // m-block: rows [wm*32, wm*32+32)
    const int jb = (warp >> 2) * 8;   // j-block: CTA-local j [jb, jb+8)

    uint32_t rank;
    asm("mov.u32 %0, %%cluster_ctarank;" : "=r"(rank));
    const int b0 = (blockIdx.x >> 2) * MB;

    // ---- W fill (fp16): tile row n = g*32 + jl -> gate row g*H + rank*32 + jl ----
    for (int e = tid; e < 128 * 192; e += NTHR) {
        int n = e & 127, k = e >> 7;
        int g = n >> 5, jl = n & 31;
        int grow = g * H_ + (int)rank * 32 + jl;
        float w = (k < 64) ? W_ih[grow * D_ + k] : W_hh[grow * H_ + (k - 64)];
        *(__half*)(smemc + OFF_W + aoff(n, k)) = __float2half_rn(w);
    }
    // zero h region of A0 (k in [64,192) = bytes [16384,49152)); A1 fully written at t=0
    for (int e = tid; e < 8192; e += NTHR)
        ((uint32_t*)(smemc + OFF_A0 + 16384))[e] = 0u;

    // ---- per-thread bias (4 gates x 2 j) ----
    float bias[4][2];
#pragma unroll
    for (int g = 0; g < 4; g++)
#pragma unroll
        for (int jj = 0; jj < 2; jj++) {
            int grow = g * H_ + (int)rank * 32 + jb + (lane & 3) * 2 + jj;
            bias[g][jj] = b_ih[grow] + b_hh[grow];
        }

    // ---- ldmatrix lane geometry (A0-relative; per-step +abuf) ----
    const int L = lane;
    const int arow = wm * 32 + ((L >> 3) & 1) * 8 + (L & 7);
    const uint32_t a_mask = (uint32_t)((arow & 7) << 4);
    const uint32_t a_k2   = (uint32_t)(((L >> 4) & 1) * 16);
    const uint32_t Abase  = sb + OFF_A0
                          + (uint32_t)((arow >> 3) * 1024 + (arow & 7) * 128);
    const int wrow = ((L >> 4) & 1) * 32 + jb + (L & 7);
    const uint32_t w_mask = (uint32_t)((wrow & 7) << 4);
    const uint32_t w_k2   = (uint32_t)(((L >> 3) & 1) * 16);
    const uint32_t Wbase  = sb + OFF_W
                          + (uint32_t)((wrow >> 3) * 1024 + (wrow & 7) * 128);

    // ---- h store addresses (k = 64 + global j of this thread's j pair) ----
    // Separate mapa per buffer: NO large offsets added to mapa'd addresses.
    const uint32_t hk = (uint32_t)(64 + (int)rank * 32 + jb + (lane & 3) * 2);
    const uint32_t h_mask  = (uint32_t)((lane >> 2) << 4);
    const uint32_t h_kpart = ((hk >> 6) << 14) + (((hk & 63) << 1) ^ h_mask);
    const uint32_t h_row   = (uint32_t)(wm * 4 * 1024 + (lane >> 2) * 128) + h_kpart;
    uint32_t hb0[CLSZ], hb1[CLSZ];
#pragma unroll
    for (int p = 0; p < CLSZ; p++) {
        hb0[p] = mapa_(sb + OFF_A0 + h_row, (uint32_t)p);
        hb1[p] = mapa_(sb + OFF_A1 + h_row, (uint32_t)p);
    }

    // ---- x geometry: thread -> (row = tid>>2, 16 dims at (tid&3)*16), A0-relative ----
    const int xrow = tid >> 2, xd = (tid & 3) * 16;
    const uint32_t x_mask = (uint32_t)((xrow & 7) << 4);
    const uint32_t x_base = sb + OFF_A0
                          + (uint32_t)((xrow >> 3) * 1024 + (xrow & 7) * 128);
    const uint32_t xc0 = x_base + (((uint32_t)(xd * 2)) ^ x_mask);
    const uint32_t xc1 = x_base + (((uint32_t)(xd * 2 + 16)) ^ x_mask);
    const float* xptr = state + (size_t)(b0 + xrow) * T_ * D_ + xd;

    // ---- x_0 into A0 ----
    {
        float xv[16];
#pragma unroll
        for (int i = 0; i < 4; i++) *(float4*)(xv + 4 * i) = *(const float4*)(xptr + 4 * i);
        uint32_t xh[8];
#pragma unroll
        for (int p = 0; p < 8; p++) xh[p] = hf2(xv[2 * p], xv[2 * p + 1]);
        stv4(xc0, xh); stv4(xc1, xh + 4);
    }

    __syncthreads();
    cluster_sync_();

    float cst[8];     // [m*4 + half*2 + jj]
#pragma unroll
    for (int i = 0; i < 8; i++) cst[i] = 0.0f;

    for (int t = 0; t < T_; t++) {
        const uint32_t abuf = (uint32_t)(t & 1) * TILE;   // GEMM reads this buffer
        const uint32_t obuf = TILE - abuf;                // stores target the other

        // prefetch x_{t+1} (completes under the GEMM)
        float xv[16];
        if (t < T_ - 1) {
            const float* xp = xptr + (size_t)(t + 1) * D_;
#pragma unroll
            for (int i = 0; i < 4; i++) *(float4*)(xv + 4 * i) = *(const float4*)(xp + 4 * i);
        }

        // ---- GEMM: acc[m][g] = bias; single fp16 combo over 12 k16 chunks ----
        float acc[2][4][4];
#pragma unroll
        for (int m = 0; m < 2; m++)
#pragma unroll
            for (int g = 0; g < 4; g++) {
                acc[m][g][0] = bias[g][0]; acc[m][g][1] = bias[g][1];
                acc[m][g][2] = bias[g][0]; acc[m][g][3] = bias[g][1];
            }

#pragma unroll
        for (int kt = 0; kt < 12; kt++) {
            const int k = kt * 16;
            const uint32_t kc = (uint32_t)((k >> 6) * 16384);
            const uint32_t K2 = (uint32_t)((k & 63) * 2);
            const uint32_t ao = abuf + kc + ((K2 + a_k2) ^ a_mask);
            const uint32_t wo = kc + ((K2 + w_k2) ^ w_mask);
            uint32_t Ah[2][4], Wh[2][4];
            ldm4(Ah[0], Abase + ao);
            ldm4(Ah[1], Abase + ao + 2048);
            ldm4(Wh[0], Wbase + wo);
            ldm4(Wh[1], Wbase + wo + 8192);
#pragma unroll
            for (int m = 0; m < 2; m++)
#pragma unroll
                for (int g = 0; g < 4; g++)
                    mma_f16(acc[m][g], Ah[m], &Wh[g >> 1][(g & 1) * 2]);
        }

        // ---- activations (8 cells: 2m x 2half x 2j), tanh.approx ----
        uint32_t hp[4];   // per (m,half): packed j-pair
#pragma unroll
        for (int m = 0; m < 2; m++)
#pragma unroll
            for (int hf = 0; hf < 2; hf++) {
                float hvj[2];
#pragma unroll
                for (int jj = 0; jj < 2; jj++) {
                    int q = hf * 2 + jj;
                    float gi = acc[m][0][q], gf = acc[m][1][q];
                    float gg = acc[m][2][q], go = acc[m][3][q];
                    int ci = m * 4 + hf * 2 + jj;
                    float cn = sigt(gf) * cst[ci] + sigt(gi) * tanht(gg);
                    cst[ci] = cn;
                    hvj[jj] = sigt(go) * tanht(cn);
                }
                hp[m * 2 + hf] = hf2(hvj[0], hvj[1]);
            }

        // ---- scatter h_t to all 4 CTAs' WRITE buffer; x_{t+1} locally ----
        // (write buffer = read buffer of step t-1; all t-1 reads completed before
        //  the sync at end of step t-1, so no wait is needed here)
        const uint32_t* hbw = (t & 1) ? hb0 : hb1;
#pragma unroll
        for (int p = 0; p < CLSZ; p++)
#pragma unroll
            for (int mh = 0; mh < 4; mh++)
                stc32(hbw[p] + (uint32_t)(mh * 1024), hp[mh]);
        if (t < T_ - 1) {
            uint32_t xh[8];
#pragma unroll
            for (int p = 0; p < 8; p++) xh[p] = hf2(xv[2 * p], xv[2 * p + 1]);
            stv4(xc0 + obuf, xh); stv4(xc1 + obuf, xh + 4);
        }

        cluster_sync_();   // single sync: writes visible AND peers' reads complete
    }

    // ---- FC: out = tanh(h @ W_fc^T + b_fc); final h written at t=511 -> A0 ----
    if (warp < A_) {
        int r = (int)rank * 32 + lane;
        float acc = b_fc[warp];
        const float* wf = W_fc + warp * H_;
#pragma unroll 8
        for (int j = 0; j < H_; j++) {
            float h = __half2float(*(const __half*)(smemc + OFF_A0 + aoff(r, 64 + j)));
            acc += h * wf[j];
        }
        out[(size_t)(b0 + r) * A_ + warp] = tanhf(acc);
    }
}

extern "C" void kernel_launch(void* const* d_in, const int* in_sizes, int n_in,
                              void* d_out, int out_size) {
    (void)in_sizes; (void)n_in; (void)out_size;
    cudaFuncSetAttribute(lstm_mma_kernel,
                         cudaFuncAttributeMaxDynamicSharedMemorySize, SMEM_BYTES);
    lstm_mma_kernel<<<(B_ / MB) * CLSZ, NTHR, SMEM_BYTES>>>(
        (const float*)d_in[0], (const float*)d_in[1], (const float*)d_in[2],
        (const float*)d_in[3], (const float*)d_in[4], (const float*)d_in[5],
        (const float*)d_in[6], (float*)d_out);
}